// round 9
// baseline (speedup 1.0000x reference)
#include <cuda_runtime.h>
#include <cstdint>

// ---------------------------------------------------------------------------
// DLRM forward, fp32. R9: occupancy-focused GEMM re-tile.
//   - 64x64 CTA tile, 128 threads (TM=4 x TN=8), acc packed along N (FFMA2
//     B-pair comes straight from LDS.128 of the W tile).
//   - smem ping-pong double buffering: ONE __syncthreads per k-tile.
//   - grids: 1024/512 CTAs for the big layers -> 4+ CTAs/SM.
// Pipeline:
//   init: detect int64 vs int32 indices + build pair LUT (device side)
//   bot MLP: 13->512->256->64    -> writes R[:,0:64]
//   interaction (FUSED gather+mean+351 pairwise dots) -> R[:,64:415]
//   top MLP: 415->512->256, 256->1 (warp GEMV)        -> d_out
// ---------------------------------------------------------------------------

#define BATCH 8192
#define NTAB  26
#define DDIM  64
#define LBAG  4
#define NROWS 100001
#define NFEAT 27           // 1 + NTAB
#define NPAIR 351          // 27*26/2
#define RCOLS 415          // 64 + 351

// Scratch (static device allocations only — no cudaMalloc allowed)
__device__ float g_h0[BATCH * 512];
__device__ float g_h1[BATCH * 256];
__device__ float g_R [(size_t)BATCH * RCOLS];
__device__ float g_t0[BATCH * 512];
__device__ float g_t1[BATCH * 256];
__device__ int   g_is64;
__device__ unsigned char g_pi[NPAIR];
__device__ unsigned char g_pj[NPAIR];

// ---------------------------------------------------------------------------
// f32x2 packed helpers (FFMA2 — ptxas never emits this from C++)
// ---------------------------------------------------------------------------
union F4U { float4 f; unsigned long long u[2]; };

__device__ __forceinline__ unsigned long long pack2(float x, float y) {
    unsigned long long r;
    asm("mov.b64 %0, {%1, %2};" : "=l"(r) : "f"(x), "f"(y));
    return r;
}
__device__ __forceinline__ void unpack2(unsigned long long v, float& x, float& y) {
    asm("mov.b64 {%0, %1}, %2;" : "=f"(x), "=f"(y) : "l"(v));
}
__device__ __forceinline__ unsigned long long ffma2(unsigned long long a,
                                                    unsigned long long b,
                                                    unsigned long long c) {
    unsigned long long d;
    asm("fma.rn.f32x2 %0, %1, %2, %3;" : "=l"(d) : "l"(a), "l"(b), "l"(c));
    return d;
}

// ---------------------------------------------------------------------------
// Init: (a) index dtype detection; (b) tril pair LUT. Same work every call.
// ---------------------------------------------------------------------------
__global__ void init_kernel(const long long* __restrict__ lsi) {
    if (threadIdx.x == 0) {
        int ok = 1;
        for (int i = 0; i < 64; i++) {
            long long v = lsi[i];
            if (v < 0 || v > 100000) { ok = 0; break; }
        }
        g_is64 = ok;
        int p = 0;
        for (int i = 1; i < NFEAT; i++)
            for (int j = 0; j < i; j++) {
                g_pi[p] = (unsigned char)i;
                g_pj[p] = (unsigned char)j;
                p++;
            }
    }
}

// ---------------------------------------------------------------------------
// Tiled SGEMM:  C[m, n] = act( sum_k A[m*K+k] * W[n*K+k] + bias[n] )
// Thread tile 4(M) x 8(N); acc[i][jp] = f32x2 pair (C[m, 2jp], C[m, 2jp+1]).
// Per kk: 1 LDS.128 (A, broadcast) + 2 LDS.128 (W, pairs used directly)
//         + 4 pack2 + 16 FFMA2.
// Smem ping-pong double buffer: one __syncthreads per k-tile.
// ---------------------------------------------------------------------------
template<int BM, int BN, int BK, bool RELU>
__global__ void __launch_bounds__((BM / 4) * (BN / 8), 4)
sgemm_bias_act(const float* __restrict__ A, const float* __restrict__ W,
               const float* __restrict__ bias, float* __restrict__ C,
               int M, int N, int K, int ldc)
{
    constexpr int THREADS = (BM / 4) * (BN / 8);
    constexpr int LA = BM * BK / THREADS;    // per-thread A elements per tile
    constexpr int LW = BN * BK / THREADS;    // per-thread W elements per tile
    __shared__ float As[2][BK][BM + 4];
    __shared__ float Ws[2][BK][BN + 4];

    const int tid  = threadIdx.x;
    const int tx   = tid % (BN / 8);
    const int ty   = tid / (BN / 8);
    const int row0 = ty * 4;
    const int col0 = tx * 8;
    const int mBase = blockIdx.y * BM;
    const int nBase = blockIdx.x * BN;

    unsigned long long acc[4][4];
    #pragma unroll
    for (int i = 0; i < 4; i++)
        #pragma unroll
        for (int j = 0; j < 4; j++) acc[i][j] = 0ull;   // bits of (0.f, 0.f)

    float pa[LA], pw[LW];

    // Load tile 0 straight into smem[0]
    #pragma unroll
    for (int q = 0; q < LA; q++) {
        int e = tid + q * THREADS;
        int k = e % BK, m = e / BK;
        As[0][k][m] = (k < K) ? A[(size_t)(mBase + m) * K + k] : 0.f;
    }
    #pragma unroll
    for (int q = 0; q < LW; q++) {
        int e = tid + q * THREADS;
        int k = e % BK, n = e / BK;
        int gn = nBase + n;
        Ws[0][k][n] = (k < K && gn < N) ? W[(size_t)gn * K + k] : 0.f;
    }
    __syncthreads();

    const int nTiles = (K + BK - 1) / BK;
    for (int t = 0; t < nTiles; t++) {
        const int buf = t & 1;

        // Prefetch next tile into registers (overlaps with compute below)
        if (t + 1 < nTiles) {
            int k0 = (t + 1) * BK;
            #pragma unroll
            for (int q = 0; q < LA; q++) {
                int e = tid + q * THREADS;
                int k = e % BK, m = e / BK;
                int gk = k0 + k;
                pa[q] = (gk < K) ? A[(size_t)(mBase + m) * K + gk] : 0.f;
            }
            #pragma unroll
            for (int q = 0; q < LW; q++) {
                int e = tid + q * THREADS;
                int k = e % BK, n = e / BK;
                int gk = k0 + k, gn = nBase + n;
                pw[q] = (gk < K && gn < N) ? W[(size_t)gn * K + gk] : 0.f;
            }
        }

        // Compute from smem[buf]
        #pragma unroll
        for (int kk = 0; kk < BK; kk++) {
            F4U a4;
            a4.f = *(const float4*)&As[buf][kk][row0];
            unsigned long long aa[4];
            aa[0] = pack2(a4.f.x, a4.f.x);
            aa[1] = pack2(a4.f.y, a4.f.y);
            aa[2] = pack2(a4.f.z, a4.f.z);
            aa[3] = pack2(a4.f.w, a4.f.w);

            F4U w0, w1;
            w0.f = *(const float4*)&Ws[buf][kk][col0];
            w1.f = *(const float4*)&Ws[buf][kk][col0 + 4];
            unsigned long long wv[4] = { w0.u[0], w0.u[1], w1.u[0], w1.u[1] };

            #pragma unroll
            for (int i = 0; i < 4; i++)
                #pragma unroll
                for (int jp = 0; jp < 4; jp++)
                    acc[i][jp] = ffma2(aa[i], wv[jp], acc[i][jp]);
        }

        // Commit prefetched tile to the other buffer, then ONE barrier
        if (t + 1 < nTiles) {
            #pragma unroll
            for (int q = 0; q < LA; q++) {
                int e = tid + q * THREADS;
                As[buf ^ 1][e % BK][e / BK] = pa[q];
            }
            #pragma unroll
            for (int q = 0; q < LW; q++) {
                int e = tid + q * THREADS;
                Ws[buf ^ 1][e % BK][e / BK] = pw[q];
            }
            __syncthreads();
        }
    }

    // Epilogue: bias + relu, scalar stores (ldc may be odd, e.g. 415)
    float bv[8];
    #pragma unroll
    for (int j = 0; j < 8; j++) {
        int gn = nBase + col0 + j;
        bv[j] = (gn < N) ? bias[gn] : 0.f;
    }
    #pragma unroll
    for (int i = 0; i < 4; i++) {
        const int gm = mBase + row0 + i;
        #pragma unroll
        for (int jp = 0; jp < 4; jp++) {
            int gn = nBase + col0 + 2 * jp;
            if (gn < N) {
                float c0, c1;
                unpack2(acc[i][jp], c0, c1);
                c0 += bv[2 * jp];
                c1 += bv[2 * jp + 1];
                if (RELU) { c0 = fmaxf(c0, 0.f); c1 = fmaxf(c1, 0.f); }
                size_t o = (size_t)gm * ldc + gn;
                C[o] = c0;
                if (gn + 1 < N) C[o + 1] = c1;
            }
        }
    }
}

// ---------------------------------------------------------------------------
// FUSED gather + interaction. One block per batch row b.
// ---------------------------------------------------------------------------
__global__ void __launch_bounds__(384)
interact_kernel(const void* __restrict__ lsi_raw,
                const float* __restrict__ emb,
                float* __restrict__ R)
{
    __shared__ float T[NFEAT][68];
    __shared__ int   rowIdx[NTAB][LBAG];
    const int b = blockIdx.x;

    if (threadIdx.x < NTAB * LBAG) {
        const int t = threadIdx.x >> 2;
        const int l = threadIdx.x & 3;
        const long long ib = (long long)t * (BATCH * LBAG) + (long long)b * LBAG + l;
        long long r = (g_is64 != 0) ? ((const long long*)lsi_raw)[ib]
                                    : (long long)((const int*)lsi_raw)[ib];
        rowIdx[t][l] = (int)r;
    }
    for (int d = threadIdx.x; d < DDIM; d += 384)
        T[0][d] = R[(size_t)b * RCOLS + d];
    __syncthreads();

    for (int e = threadIdx.x; e < NTAB * (DDIM / 2); e += 384) {
        const int t  = e >> 5;
        const int d2 = e & 31;
        const float2* tab = (const float2*)(emb + (size_t)t * NROWS * DDIM) + d2;
        float sx = 0.f, sy = 0.f;
        #pragma unroll
        for (int l = 0; l < LBAG; l++) {
            float2 v = __ldg(tab + (size_t)rowIdx[t][l] * (DDIM / 2));
            sx += v.x; sy += v.y;
        }
        *(float2*)&T[1 + t][2 * d2] = make_float2(sx * 0.25f, sy * 0.25f);
    }
    __syncthreads();

    const int p = threadIdx.x;
    if (p < NPAIR) {
        const int i = __ldg(&g_pi[p]);
        const int j = __ldg(&g_pj[p]);
        const float4* ti = (const float4*)T[i];
        const float4* tj = (const float4*)T[j];
        float s = 0.f;
        #pragma unroll
        for (int k = 0; k < DDIM / 4; k++) {
            float4 a = ti[k], c = tj[k];
            s += a.x * c.x + a.y * c.y + a.z * c.z + a.w * c.w;
        }
        R[(size_t)b * RCOLS + DDIM + p] = s;
    }
}

// ---------------------------------------------------------------------------
// Final layer: z[b] = dot(t1[b, :256], w2) + b2. One warp per row.
// ---------------------------------------------------------------------------
__global__ void final_kernel(const float* __restrict__ t1,
                             const float* __restrict__ w2,
                             const float* __restrict__ b2,
                             float* __restrict__ out)
{
    const int warp = threadIdx.x >> 5;
    const int lane = threadIdx.x & 31;
    const int b = blockIdx.x * 8 + warp;

    const float4* x = (const float4*)(t1 + (size_t)b * 256);
    const float4* w = (const float4*)w2;
    float s = 0.f;
    #pragma unroll
    for (int k = lane; k < 64; k += 32) {
        float4 a = x[k], c = w[k];
        s += a.x * c.x + a.y * c.y + a.z * c.z + a.w * c.w;
    }
    #pragma unroll
    for (int off = 16; off; off >>= 1)
        s += __shfl_xor_sync(0xFFFFFFFFu, s, off);
    if (lane == 0) out[b] = s + b2[0];
}

// ---------------------------------------------------------------------------
// Launch
// ---------------------------------------------------------------------------
extern "C" void kernel_launch(void* const* d_in, const int* in_sizes, int n_in,
                              void* d_out, int out_size)
{
    const float* dense = (const float*)d_in[0];
    const void*  lsi   = d_in[2];                 // int64 or int32 (detected)
    const float* emb   = (const float*)d_in[3];
    const float* bw0 = (const float*)d_in[4];
    const float* bb0 = (const float*)d_in[5];
    const float* bw1 = (const float*)d_in[6];
    const float* bb1 = (const float*)d_in[7];
    const float* bw2 = (const float*)d_in[8];
    const float* bb2 = (const float*)d_in[9];
    const float* tw0 = (const float*)d_in[10];
    const float* tb0 = (const float*)d_in[11];
    const float* tw1 = (const float*)d_in[12];
    const float* tb1 = (const float*)d_in[13];
    const float* tw2 = (const float*)d_in[14];
    const float* tb2 = (const float*)d_in[15];

    float *h0, *h1, *R, *t0, *t1;
    cudaGetSymbolAddress((void**)&h0, g_h0);
    cudaGetSymbolAddress((void**)&h1, g_h1);
    cudaGetSymbolAddress((void**)&R,  g_R);
    cudaGetSymbolAddress((void**)&t0, g_t0);
    cudaGetSymbolAddress((void**)&t1, g_t1);

    init_kernel<<<1, 1>>>((const long long*)lsi);

    // Bottom MLP: 13 -> 512 -> 256 -> 64 (last layer writes R[:, 0:64])
    sgemm_bias_act<64, 64, 16, true><<<dim3(8, 128), 128>>>(
        dense, bw0, bb0, h0, BATCH, 512, 13, 512);
    sgemm_bias_act<64, 64, 16, true><<<dim3(4, 128), 128>>>(
        h0, bw1, bb1, h1, BATCH, 256, 512, 256);
    sgemm_bias_act<32, 64, 16, true><<<dim3(1, 256), 64>>>(
        h1, bw2, bb2, R, BATCH, 64, 256, RCOLS);

    // Fused gather + pairwise interaction -> R[:, 64:415]
    interact_kernel<<<BATCH, 384>>>(lsi, emb, R);

    // Top MLP: 415 -> 512 -> 256 -> 1
    sgemm_bias_act<64, 64, 16, true><<<dim3(8, 128), 128>>>(
        R, tw0, tb0, t0, BATCH, 512, RCOLS, 512);
    sgemm_bias_act<64, 64, 16, true><<<dim3(4, 128), 128>>>(
        t0, tw1, tb1, t1, BATCH, 256, 512, 256);
    final_kernel<<<BATCH / 8, 256>>>(t1, tw2, tb2, (float*)d_out);
}